// round 1
// baseline (speedup 1.0000x reference)
#include <cuda_runtime.h>
#include <cuda_bf16.h>
#include <cstdint>

// B2Q_Net: mathematically, the window-softmax sums to 1 over its axis, so the
// Nw-window aggregate is exactly 20.0 on the interior [HALF, T-HALF] and smaller
// at the edges. phase is therefore a giant tie; stable top_k returns
// [HALF, HALF+1, ..., HALF+k-1] and gathered = frame_feature[HALF : HALF+k],
// which is a contiguous block (layout (T,B=1,C) row-major).
//
// Kernel = one contiguous 512KB copy + 64 index writes.

static constexpr int NW     = 20;
static constexpr int HALF   = NW / 2;
static constexpr int NTOKEN = 64;
static constexpr int NCLASS = 10;

// Vectorized contiguous copy: dst[0 : n4) <- src[0 : n4) in float4 units.
__global__ void copy_f4_kernel(const float4* __restrict__ src,
                               float4* __restrict__ dst, int n4) {
    int i = blockIdx.x * blockDim.x + threadIdx.x;
    int stride = gridDim.x * blockDim.x;
    for (; i < n4; i += stride) {
        dst[i] = src[i];
    }
}

// Scalar tail copy (in case k*C is not divisible by 4 — not expected, but safe).
__global__ void copy_f1_kernel(const float* __restrict__ src,
                               float* __restrict__ dst, int n) {
    int i = blockIdx.x * blockDim.x + threadIdx.x;
    if (i < n) dst[i] = src[i];
}

// Write the top-k indices (value-cast to float): t0, t0+1, ..., t0+k-1.
__global__ void write_idx_kernel(float* __restrict__ out, int k, int t0) {
    int i = blockIdx.x * blockDim.x + threadIdx.x;
    if (i < k) out[i] = (float)(t0 + i);
}

extern "C" void kernel_launch(void* const* d_in, const int* in_sizes, int n_in,
                              void* d_out, int out_size) {
    const float* frame = (const float*)d_in[0];   // (T, 1, C) fp32
    // Wg is (C, NCLASS) -> C from its element count.
    const int C = in_sizes[1] / NCLASS;           // 2048
    const int T = in_sizes[0] / C;                // 16384 (B == 1)
    const int k = (T < NTOKEN) ? T : NTOKEN;      // 64
    const int t0 = HALF;                          // 10

    float* out = (float*)d_out;
    const long long gathered_elems = (long long)k * C;   // 131072

    if (out_size >= (int)gathered_elems) {
        // gathered = frame[t0 : t0+k] — contiguous rows.
        const float* src = frame + (long long)t0 * C;
        int n = (int)gathered_elems;
        int n4 = n >> 2;
        if (n4 > 0) {
            int threads = 256;
            int blocks = (n4 + threads - 1) / threads;
            if (blocks > 1024) blocks = 1024;
            copy_f4_kernel<<<blocks, threads>>>((const float4*)src,
                                                (float4*)out, n4);
        }
        int tail = n - (n4 << 2);
        if (tail > 0) {
            copy_f1_kernel<<<1, 32>>>(src + (n4 << 2), out + (n4 << 2), tail);
        }
        // Remaining elements (if any) are the top_idx, value-cast to float.
        int rem = out_size - n;
        if (rem > 0) {
            int nk = rem < k ? rem : k;
            write_idx_kernel<<<1, 64>>>(out + n, nk, t0);
            // If out_size is larger than gathered+k (unexpected), zero-fill rest.
            if (rem > k) {
                int extra = rem - k;
                copy_f1_kernel<<<(extra + 255) / 256, 256>>>(out + n + k,
                                                             out + n + k, 0);
                // (no-op guard; real zero fill below)
                cudaMemsetAsync(out + n + k, 0, (size_t)extra * sizeof(float));
            }
        }
    } else {
        // out is only the indices (or a prefix thereof).
        int nk = out_size < k ? out_size : k;
        write_idx_kernel<<<1, 64>>>(out, nk, t0);
    }
}

// round 3
// speedup vs baseline: 1.1237x; 1.1237x over previous
#include <cuda_runtime.h>
#include <cuda_bf16.h>
#include <cstdint>

// B2Q_Net: mathematically, the window-softmax sums to 1 over its axis, so the
// Nw-window aggregate is exactly 20.0 on the interior [HALF, T-HALF] and smaller
// at the edges. phase is therefore a giant tie; stable top_k returns
// [HALF, HALF+1, ..., HALF+k-1] and gathered = frame_feature[HALF : HALF+k],
// which is a contiguous block (layout (T,B=1,C) row-major).
//
// Kernel = one contiguous 512KB copy + 64 index writes.

static constexpr int NW     = 20;
static constexpr int HALF   = NW / 2;
static constexpr int NTOKEN = 64;
static constexpr int NCLASS = 10;

// Vectorized contiguous copy: dst[0 : n4) <- src[0 : n4) in float4 units.
__global__ void copy_f4_kernel(const float4* __restrict__ src,
                               float4* __restrict__ dst, int n4) {
    int i = blockIdx.x * blockDim.x + threadIdx.x;
    int stride = gridDim.x * blockDim.x;
    for (; i < n4; i += stride) {
        dst[i] = src[i];
    }
}

// Scalar tail copy (in case k*C is not divisible by 4 — not expected, but safe).
__global__ void copy_f1_kernel(const float* __restrict__ src,
                               float* __restrict__ dst, int n) {
    int i = blockIdx.x * blockDim.x + threadIdx.x;
    if (i < n) dst[i] = src[i];
}

// Write the top-k indices (value-cast to float): t0, t0+1, ..., t0+k-1.
__global__ void write_idx_kernel(float* __restrict__ out, int k, int t0) {
    int i = blockIdx.x * blockDim.x + threadIdx.x;
    if (i < k) out[i] = (float)(t0 + i);
}

extern "C" void kernel_launch(void* const* d_in, const int* in_sizes, int n_in,
                              void* d_out, int out_size) {
    const float* frame = (const float*)d_in[0];   // (T, 1, C) fp32
    // Wg is (C, NCLASS) -> C from its element count.
    const int C = in_sizes[1] / NCLASS;           // 2048
    const int T = in_sizes[0] / C;                // 16384 (B == 1)
    const int k = (T < NTOKEN) ? T : NTOKEN;      // 64
    const int t0 = HALF;                          // 10

    float* out = (float*)d_out;
    const long long gathered_elems = (long long)k * C;   // 131072

    if (out_size >= (int)gathered_elems) {
        // gathered = frame[t0 : t0+k] — contiguous rows.
        const float* src = frame + (long long)t0 * C;
        int n = (int)gathered_elems;
        int n4 = n >> 2;
        if (n4 > 0) {
            int threads = 256;
            int blocks = (n4 + threads - 1) / threads;
            if (blocks > 1024) blocks = 1024;
            copy_f4_kernel<<<blocks, threads>>>((const float4*)src,
                                                (float4*)out, n4);
        }
        int tail = n - (n4 << 2);
        if (tail > 0) {
            copy_f1_kernel<<<1, 32>>>(src + (n4 << 2), out + (n4 << 2), tail);
        }
        // Remaining elements (if any) are the top_idx, value-cast to float.
        int rem = out_size - n;
        if (rem > 0) {
            int nk = rem < k ? rem : k;
            write_idx_kernel<<<1, 64>>>(out + n, nk, t0);
            // If out_size is larger than gathered+k (unexpected), zero-fill rest.
            if (rem > k) {
                int extra = rem - k;
                copy_f1_kernel<<<(extra + 255) / 256, 256>>>(out + n + k,
                                                             out + n + k, 0);
                // (no-op guard; real zero fill below)
                cudaMemsetAsync(out + n + k, 0, (size_t)extra * sizeof(float));
            }
        }
    } else {
        // out is only the indices (or a prefix thereof).
        int nk = out_size < k ? out_size : k;
        write_idx_kernel<<<1, 64>>>(out, nk, t0);
    }
}

// round 4
// speedup vs baseline: 1.1534x; 1.0265x over previous
#include <cuda_runtime.h>
#include <cuda_bf16.h>
#include <cstdint>

// B2Q_Net: the window-softmax sums to 1 over its axis, so the Nw-window
// aggregate is exactly 20.0 on the interior; phase is a giant tie and stable
// top_k returns [HALF .. HALF+k-1]. gathered = frame_feature[HALF : HALF+k],
// a contiguous 512KB block. Verified bit-exact (rel_err = 0.0) in R3.
//
// R3 showed wall time is launch-node overhead (write_idx_kernel: 3.3us for a
// 256-byte write). Fuse copy + index-write into ONE kernel node.

static constexpr int NW     = 20;
static constexpr int HALF   = NW / 2;
static constexpr int NTOKEN = 64;
static constexpr int NCLASS = 10;

// Fused: thread i copies float4 i (i < n4); threads [0, nk) also write the
// top_idx values (cast to float) at out + idx_off.
__global__ void fused_gather_idx_kernel(const float4* __restrict__ src,
                                        float4* __restrict__ dst, int n4,
                                        float* __restrict__ idx_out, int nk,
                                        int t0) {
    int i = blockIdx.x * blockDim.x + threadIdx.x;
    if (i < n4) dst[i] = src[i];
    if (i < nk) idx_out[i] = (float)(t0 + i);
}

// Fallback scalar path (only used if out_size doesn't match the expected
// gathered layout — not expected for this problem).
__global__ void fallback_kernel(const float* __restrict__ src,
                                float* __restrict__ out, int n_copy,
                                int nk, int idx_off, int t0) {
    int i = blockIdx.x * blockDim.x + threadIdx.x;
    if (i < n_copy) out[i] = src[i];
    if (i < nk) out[idx_off + i] = (float)(t0 + i);
}

extern "C" void kernel_launch(void* const* d_in, const int* in_sizes, int n_in,
                              void* d_out, int out_size) {
    const float* frame = (const float*)d_in[0];   // (T, 1, C) fp32
    const int C = in_sizes[1] / NCLASS;           // 2048 (Wg is (C, NCLASS))
    const int T = in_sizes[0] / C;                // 16384
    const int k = (T < NTOKEN) ? T : NTOKEN;      // 64
    const int t0 = HALF;                          // 10

    float* out = (float*)d_out;
    const long long gathered_elems = (long long)k * C;   // 131072

    if (out_size >= (int)gathered_elems && ((k * C) & 3) == 0 && ((C & 3) == 0)) {
        const float* src = frame + (long long)t0 * C;
        int n = (int)gathered_elems;
        int n4 = n >> 2;                          // 32768
        int rem = out_size - n;                   // index elements present
        int nk = rem < k ? rem : k;
        if (nk < 0) nk = 0;

        int threads = 256;
        int blocks = (n4 + threads - 1) / threads; // 128
        fused_gather_idx_kernel<<<blocks, threads>>>(
            (const float4*)src, (float4*)out, n4, out + n, nk, t0);
    } else {
        // Unexpected layout: scalar fused fallback.
        int n_copy = out_size < (int)gathered_elems ? 0 : (int)gathered_elems;
        const float* src = frame + (long long)t0 * C;
        int rem = out_size - n_copy;
        int nk = rem < k ? rem : k;
        if (nk < 0) nk = 0;
        int total = n_copy > nk ? n_copy : nk;
        if (total == 0) total = 1;
        fallback_kernel<<<(total + 255) / 256, 256>>>(src, out, n_copy, nk,
                                                      n_copy, t0);
    }
}

// round 6
// speedup vs baseline: 1.3711x; 1.1887x over previous
#include <cuda_runtime.h>
#include <cuda_bf16.h>
#include <cstdint>

// B2Q_Net: window-softmax sums to 1 -> Nw-window aggregate is exactly 20.0 on
// the interior -> phase is a giant tie -> stable top_k = [HALF .. HALF+k-1].
// gathered = frame_feature[HALF : HALF+k], one contiguous 512KB block.
// Verified bit-exact (rel_err = 0.0) in R3/R4.
//
// R5 was an infra failure; this re-benches the R4-proposed kernel:
// single node, MLP=2 per thread, zero bounds checks in the exact-shape path.
// Idx write moved to the LAST block so the extra work rides the wave tail.

static constexpr int NW     = 20;
static constexpr int HALF   = NW / 2;
static constexpr int NTOKEN = 64;
static constexpr int NCLASS = 10;

static constexpr int EX_BLOCKS  = 64;
static constexpr int EX_THREADS = 256;
static constexpr int EX_STRIDE  = EX_BLOCKS * EX_THREADS;   // 16384

// Exact-shape kernel: n4 == 2 * EX_STRIDE (32768 float4 = 512KB). Each thread
// issues 2 independent LDG.128 before storing (MLP=2, one scoreboard wait).
// Last block's lanes [0,64) also emit the top_idx values.
__global__ void __launch_bounds__(EX_THREADS, 1)
fused_copy_exact(const float4* __restrict__ src, float4* __restrict__ dst,
                 float* __restrict__ idx_out) {
    int i = blockIdx.x * EX_THREADS + threadIdx.x;
    float4 a = src[i];
    float4 b = src[i + EX_STRIDE];
    dst[i] = a;
    dst[i + EX_STRIDE] = b;
    if (blockIdx.x == EX_BLOCKS - 1 && threadIdx.x < NTOKEN) {
        idx_out[threadIdx.x] = (float)(HALF + threadIdx.x);
    }
}

// Generic fallback (any shape): scalar copy + idx write, fused.
__global__ void fallback_kernel(const float* __restrict__ src,
                                float* __restrict__ out, int n_copy,
                                int nk, int idx_off, int t0) {
    int i = blockIdx.x * blockDim.x + threadIdx.x;
    if (i < n_copy) out[i] = src[i];
    if (i < nk) out[idx_off + i] = (float)(t0 + i);
}

extern "C" void kernel_launch(void* const* d_in, const int* in_sizes, int n_in,
                              void* d_out, int out_size) {
    const float* frame = (const float*)d_in[0];   // (T, 1, C) fp32
    const int C = in_sizes[1] / NCLASS;           // 2048 (Wg is (C, NCLASS))
    const int T = in_sizes[0] / C;                // 16384
    const int k = (T < NTOKEN) ? T : NTOKEN;      // 64
    const int t0 = HALF;                          // 10

    float* out = (float*)d_out;
    const long long gathered_elems = (long long)k * C;   // 131072
    const int n = (int)gathered_elems;
    const int n4 = n >> 2;                                // 32768

    const bool exact = (k == NTOKEN) && ((C & 3) == 0) &&
                       (n4 == 2 * EX_STRIDE) &&
                       (out_size >= n + k);

    if (exact) {
        const float* src = frame + (long long)t0 * C;     // 128B-aligned
        fused_copy_exact<<<EX_BLOCKS, EX_THREADS>>>(
            (const float4*)src, (float4*)out, out + n);
    } else {
        int n_copy = out_size < n ? 0 : n;
        const float* src = frame + (long long)t0 * C;
        int rem = out_size - n_copy;
        int nk = rem < k ? rem : k;
        if (nk < 0) nk = 0;
        int total = n_copy > nk ? n_copy : nk;
        if (total == 0) total = 1;
        fallback_kernel<<<(total + 255) / 256, 256>>>(src, out, n_copy, nk,
                                                      n_copy, t0);
    }
}